// round 4
// baseline (speedup 1.0000x reference)
#include <cuda_runtime.h>
#include <cstdint>

// Problem constants (fixed by the reference)
#define NN      2048
#define DF      512
#define MSUP    512
#define NPAIRS  2096128       // N*(N-1)/2
#define TARGET  1536          // N - NUM_SUPER merges
#define MAXDEG  512

// rank table: inter in [0,64), union in [0,128)
#define TI      64
#define TU      128
#define NCOMB   (TI*TU)       // 8192
#define SPLIT   512           // idx>>13 gives 9 bits
#define NSB     (NCOMB*SPLIT) // 4194304 sub-buckets
#define NPART   4096          // NSB / 1024

// Output layout: X_coarse [512,512] | A_coarse [512,512] | P [2048,512]
#define XC_OFF  0
#define AC_OFF  262144
#define P_OFF   524288
#define OUT_N   1572864

// -------- scratch (device globals; no allocation allowed) --------
__device__ int      g_adj[NN * MAXDEG];    // 4 MB
__device__ int      g_deg[NN];
__device__ int      g_inter[NN * NN];      // 16 MB (upper triangle)
__device__ unsigned g_rank[NCOMB];
__device__ unsigned g_hist[NSB];           // 16 MB
__device__ unsigned g_off[NSB];            // 16 MB
__device__ unsigned g_base[NSB];           // 16 MB
__device__ unsigned g_part[NPART];
__device__ unsigned g_partoff[NPART];
__device__ int      g_npos;
__device__ unsigned g_sorted[NPAIRS];      // 8 MB
__device__ int      g_labels[NN];
__device__ float    g_wnode[NN];

// -------- 1) adjacency lists + degrees (warp per row, ascending j) --------
__global__ void k_adj(const float* __restrict__ A) {
    int warp = (blockIdx.x * blockDim.x + threadIdx.x) >> 5;
    int lane = threadIdx.x & 31;
    if (warp >= NN) return;
    const float* row = A + (size_t)warp * NN;
    int cnt = 0;
    for (int k = 0; k < NN; k += 32) {
        float v = row[k + lane];
        unsigned b = __ballot_sync(0xFFFFFFFFu, v > 0.0f);
        if (v > 0.0f) {
            int pos = cnt + __popc(b & ((1u << lane) - 1u));
            if (pos < MAXDEG) g_adj[warp * MAXDEG + pos] = k + lane;
        }
        cnt += __popc(b);
    }
    if (lane == 0) g_deg[warp] = cnt;
}

// -------- 2) zero scratch --------
__global__ void k_zeroscratch() {
    size_t t = (size_t)blockIdx.x * blockDim.x + threadIdx.x;
    size_t stride = (size_t)gridDim.x * blockDim.x;
    int4 z = make_int4(0, 0, 0, 0);
    for (size_t i = t; i < (size_t)NN * NN / 4; i += stride)
        reinterpret_cast<int4*>(g_inter)[i] = z;
    for (size_t i = t; i < NSB / 4; i += stride) {
        reinterpret_cast<int4*>(g_hist)[i] = z;
        reinterpret_cast<int4*>(g_off)[i] = z;
    }
}

// -------- 3) sparse triangle counting --------
__global__ void k_tri() {
    int warp = (blockIdx.x * blockDim.x + threadIdx.x) >> 5;
    int lane = threadIdx.x & 31;
    if (warp >= NN) return;
    int d = min(g_deg[warp], MAXDEG);
    const int* nb = &g_adj[warp * MAXDEG];
    for (int a = 0; a < d - 1; a++) {
        int i = nb[a];                    // ascending => i < j below
        int* irow = &g_inter[i * NN];
        for (int b = a + 1 + lane; b < d; b += 32)
            atomicAdd(&irow[nb[b]], 1);
    }
}

// -------- 4) rank by counting: rank(c) = #{c' : val(c') > val(c)} --------
// Monotone in jaccard descending; equal floats share a rank. Fully parallel.
__global__ void k_rank() {
    __shared__ unsigned vals[NCOMB];      // 32 KB
    __shared__ unsigned cnt[16];
    int tid = threadIdx.x;
    for (int k = 0; k < 8; k++) {
        int v = tid * 8 + k;
        int i = v >> 7, u = v & (TU - 1);
        float jac = (u == 0) ? 0.0f : __fdiv_rn((float)i, (float)u);
        vals[v] = __float_as_uint(jac);   // >= +0 => bits monotone
    }
    if (tid < 16) cnt[tid] = 0;
    __syncthreads();
    int c = blockIdx.x * 16 + (tid >> 6);
    int seg = tid & 63;
    unsigned myv = vals[c];
    unsigned n = 0;
    #pragma unroll 8
    for (int x = seg * 128; x < seg * 128 + 128; x++)
        n += (vals[x] > myv);
    atomicAdd(&cnt[tid >> 6], n);
    __syncthreads();
    if (tid < 16) g_rank[blockIdx.x * 16 + tid] = cnt[tid];
}

// -------- 5) count positives per sub-bucket --------
__device__ __forceinline__ unsigned sbid_of(int inter, int uni, unsigned idx) {
    int ic = min(inter, TI - 1), uc = min(uni, TU - 1);
    return g_rank[ic * TU + uc] * SPLIT + (idx >> 13);
}

__global__ void k_count() {
    __shared__ int sdeg[NN];
    int i = blockIdx.x;
    for (int t = threadIdx.x; t < NN; t += blockDim.x) sdeg[t] = g_deg[t];
    __syncthreads();
    if (i >= NN - 1) return;
    int di = sdeg[i];
    const int* irow = &g_inter[i * NN];
    for (int j = i + 1 + threadIdx.x; j < NN; j += blockDim.x) {
        int inter = irow[j];
        if (inter > 0) {
            unsigned idx = (unsigned)(i * NN + j);
            atomicAdd(&g_hist[sbid_of(inter, di + sdeg[j] - inter, idx)], 1u);
        }
    }
}

// -------- 6) scan over 4M sub-bucket counts (3 kernels) --------
__global__ void k_s1() {
    __shared__ unsigned s[1024];
    int tid = threadIdx.x;
    unsigned v = g_hist[blockIdx.x * 1024 + tid];
    s[tid] = v;
    __syncthreads();
    for (int d = 512; d > 0; d >>= 1) {
        if (tid < d) s[tid] += s[tid + d];
        __syncthreads();
    }
    if (tid == 0) g_part[blockIdx.x] = s[0];
}

__global__ void k_s2() {
    __shared__ unsigned s[1024];
    int tid = threadIdx.x;
    unsigned loc[4];
    unsigned sum = 0;
    #pragma unroll
    for (int k = 0; k < 4; k++) { loc[k] = g_part[tid * 4 + k]; sum += loc[k]; }
    s[tid] = sum;
    __syncthreads();
    for (int d = 1; d < 1024; d <<= 1) {
        unsigned a = (tid >= d) ? s[tid - d] : 0u;
        __syncthreads();
        s[tid] += a;
        __syncthreads();
    }
    unsigned run = s[tid] - sum;          // exclusive
    #pragma unroll
    for (int k = 0; k < 4; k++) { g_partoff[tid * 4 + k] = run; run += loc[k]; }
    if (tid == 1023) g_npos = (int)s[1023];
}

__global__ void k_s3() {
    __shared__ unsigned s[1024];
    int tid = threadIdx.x;
    unsigned v = g_hist[blockIdx.x * 1024 + tid];
    s[tid] = v;
    __syncthreads();
    for (int d = 1; d < 1024; d <<= 1) {
        unsigned a = (tid >= d) ? s[tid - d] : 0u;
        __syncthreads();
        s[tid] += a;
        __syncthreads();
    }
    g_base[blockIdx.x * 1024 + tid] = g_partoff[blockIdx.x] + s[tid] - v;
}

// -------- 7) scatter positive pairs (unordered within sub-bucket) --------
__global__ void k_scatter() {
    __shared__ int sdeg[NN];
    int i = blockIdx.x;
    for (int t = threadIdx.x; t < NN; t += blockDim.x) sdeg[t] = g_deg[t];
    __syncthreads();
    if (i >= NN - 1) return;
    int di = sdeg[i];
    const int* irow = &g_inter[i * NN];
    for (int j = i + 1 + threadIdx.x; j < NN; j += blockDim.x) {
        int inter = irow[j];
        if (inter > 0) {
            unsigned idx = (unsigned)(i * NN + j);
            unsigned sb = sbid_of(inter, di + sdeg[j] - inter, idx);
            unsigned slot = atomicAdd(&g_off[sb], 1u);
            g_sorted[g_base[sb] + slot] = idx;
        }
    }
}

// -------- 8) sort within each sub-bucket (warp per bucket, parallel) --------
__global__ void k_subsort() {
    __shared__ unsigned sbuf[32][256];    // 32 KB: one 256-slot buffer per warp
    int tid = threadIdx.x, lane = tid & 31, w = tid >> 5;
    int gwarp = blockIdx.x * 32 + w;      // 8192 warps total
    unsigned wbase = (unsigned)gwarp * (NSB / 8192);   // 512 sub-buckets each

    for (int k0 = 0; k0 < NSB / 8192; k0 += 32) {
        unsigned sb0 = wbase + k0 + lane;
        unsigned v = g_hist[sb0];
        unsigned m = __ballot_sync(0xFFFFFFFFu, v > 1);
        while (m) {
            int b = __ffs(m) - 1; m &= m - 1;
            unsigned sb = wbase + k0 + b;
            unsigned s = __shfl_sync(0xFFFFFFFFu, v, b);
            unsigned base = g_base[sb];
            if (s <= 32) {
                unsigned x = (lane < (int)s) ? g_sorted[base + lane] : 0xFFFFFFFFu;
                #pragma unroll
                for (int k = 2; k <= 32; k <<= 1)
                    #pragma unroll
                    for (int j = k >> 1; j > 0; j >>= 1) {
                        unsigned x2 = __shfl_xor_sync(0xFFFFFFFFu, x, j);
                        bool lower = ((lane & j) == 0), asc = ((lane & k) == 0);
                        x = (lower == asc) ? umin(x, x2) : umax(x, x2);
                    }
                if (lane < (int)s) g_sorted[base + lane] = x;
            } else if (s <= 256) {
                for (unsigned q = lane; q < s; q += 32) sbuf[w][q] = g_sorted[base + q];
                __syncwarp();
                for (unsigned p = 0; p < s; p++) {
                    unsigned off = p & 1;
                    for (unsigned q = off + 2 * lane; q + 1 < s; q += 64) {
                        unsigned a = sbuf[w][q], bb = sbuf[w][q + 1];
                        if (a > bb) { sbuf[w][q] = bb; sbuf[w][q + 1] = a; }
                    }
                    __syncwarp();
                }
                for (unsigned q = lane; q < s; q += 32) g_sorted[base + q] = sbuf[w][q];
                __syncwarp();
            } else {
                if (lane == 0) {          // safety net (never expected)
                    for (unsigned a = 1; a < s; a++) {
                        unsigned key = g_sorted[base + a];
                        int bb = (int)a - 1;
                        while (bb >= 0 && g_sorted[base + bb] > key) {
                            g_sorted[base + bb + 1] = g_sorted[base + bb]; bb--;
                        }
                        g_sorted[base + bb + 1] = key;
                    }
                }
                __syncwarp();
            }
        }
    }
}

// -------- 9) union-find over the fully sorted positive-pair stream --------
__global__ void k_uf() {
    __shared__ int parent[NN];
    __shared__ int rmin[NN];
    __shared__ int ssz[MSUP];
    __shared__ float swc[MSUP];
    __shared__ unsigned cidx[1024];
    __shared__ int mlist[MSUP];
    __shared__ int scnt[32], soff[33];
    __shared__ int s_done, s_merged, s_mcnt;
    int tid = threadIdx.x, lane = tid & 31, w = tid >> 5;

    for (int t = tid; t < NN; t += 1024) { parent[t] = t; rmin[t] = NN; }
    for (int t = tid; t < MSUP; t += 1024) ssz[t] = 0;
    if (tid == 0) { s_done = 0; s_merged = 0; s_mcnt = 0; }
    __syncthreads();

    int npos = g_npos;
    for (int base = 0; base < npos && !s_done; base += 1024) {
        bool cand = false; unsigned idx = 0;
        if (base + tid < npos) {
            idx = g_sorted[base + tid];
            int i = idx >> 11, j = idx & (NN - 1);
            int ri = i; while (parent[ri] != ri) ri = parent[ri];
            int rj = j; while (parent[rj] != rj) rj = parent[rj];
            cand = (ri != rj);
        }
        unsigned b = __ballot_sync(0xFFFFFFFFu, cand);
        if (lane == 0) scnt[w] = __popc(b);
        __syncthreads();
        if (tid == 0) {
            int acc = 0;
            #pragma unroll
            for (int k2 = 0; k2 < 32; k2++) { soff[k2] = acc; acc += scnt[k2]; }
            soff[32] = acc;
        }
        __syncthreads();
        if (cand) cidx[soff[w] + __popc(b & ((1u << lane) - 1u))] = idx;
        __syncthreads();
        if (tid == 0) {
            int nc = soff[32];
            for (int c = 0; c < nc; c++) {
                unsigned id = cidx[c];
                int a = id >> 11, bb = id & (NN - 1);
                int ra = a;  while (parent[ra] != ra) { parent[ra] = parent[parent[ra]]; ra = parent[ra]; }
                int rb = bb; while (parent[rb] != rb) { parent[rb] = parent[parent[rb]]; rb = parent[rb]; }
                if (ra != rb) {
                    parent[rb] = ra;
                    if (++s_merged == TARGET) { s_done = 1; break; }
                }
            }
        }
        __syncthreads();
    }

    // zero-jaccard fallback in natural (i,j) order (skips positives)
    if (!s_done) {
        for (int i = 0; i < NN - 1 && !s_done; i++) {
            const int* irow = &g_inter[i * NN];
            for (int jb = i + 1; jb < NN && !s_done; jb += 1024) {
                int j = jb + tid;
                bool cand = false;
                if (j < NN && irow[j] == 0) {
                    int ri = i; while (parent[ri] != ri) ri = parent[ri];
                    int rj = j; while (parent[rj] != rj) rj = parent[rj];
                    cand = (ri != rj);
                }
                unsigned b = __ballot_sync(0xFFFFFFFFu, cand);
                if (lane == 0) scnt[w] = __popc(b);
                __syncthreads();
                if (tid == 0) {
                    int acc = 0;
                    #pragma unroll
                    for (int k2 = 0; k2 < 32; k2++) { soff[k2] = acc; acc += scnt[k2]; }
                    soff[32] = acc;
                }
                __syncthreads();
                if (cand) cidx[soff[w] + __popc(b & ((1u << lane) - 1u))] = (unsigned)(i * NN + j);
                __syncthreads();
                if (tid == 0) {
                    int nc = soff[32];
                    for (int c = 0; c < nc; c++) {
                        unsigned id = cidx[c];
                        int a = id >> 11, bb = id & (NN - 1);
                        int ra = a;  while (parent[ra] != ra) { parent[ra] = parent[parent[ra]]; ra = parent[ra]; }
                        int rb = bb; while (parent[rb] != rb) { parent[rb] = parent[parent[rb]]; rb = parent[rb]; }
                        if (ra != rb) {
                            parent[rb] = ra;
                            if (++s_merged == TARGET) { s_done = 1; break; }
                        }
                    }
                }
                __syncthreads();
            }
        }
    }
    __syncthreads();

    // -------- parallel labeling: label = rank of component's min node --------
    for (int t = tid; t < NN; t += 1024) {
        int r = t; while (parent[r] != r) r = parent[r];
        atomicMin(&rmin[r], t);
    }
    __syncthreads();
    for (int t = tid; t < NN; t += 1024) {
        int r = t; while (parent[r] != r) r = parent[r];
        if (rmin[r] == t) mlist[atomicAdd(&s_mcnt, 1)] = t;   // exactly MSUP minima
    }
    __syncthreads();
    // bitonic sort mlist[512] ascending
    for (int k = 2; k <= MSUP; k <<= 1)
        for (int j = k >> 1; j > 0; j >>= 1) {
            for (int t = tid; t < MSUP; t += 1024) {
                int x = t ^ j;
                if (x > t) {
                    int a = mlist[t], b = mlist[x];
                    if (((t & k) == 0) ? (a > b) : (a < b)) { mlist[t] = b; mlist[x] = a; }
                }
            }
            __syncthreads();
        }
    for (int t = tid; t < NN; t += 1024) {
        int r = t; while (parent[r] != r) r = parent[r];
        int m = rmin[r];
        int lo = 0, hi = MSUP - 1;
        while (lo < hi) { int mid = (lo + hi) >> 1; if (mlist[mid] < m) lo = mid + 1; else hi = mid; }
        g_labels[t] = lo;
        atomicAdd(&ssz[lo], 1);
    }
    __syncthreads();
    for (int t = tid; t < MSUP; t += 1024)
        swc[t] = 1.0f / sqrtf((float)ssz[t] + 1e-10f);
    __syncthreads();
    for (int t = tid; t < NN; t += 1024)
        g_wnode[t] = swc[g_labels[t]];
}

// -------- 10) epilogue --------
__global__ void k_zero(float* out) {
    int t = blockIdx.x * blockDim.x + threadIdx.x;
    float4 z = make_float4(0.f, 0.f, 0.f, 0.f);
    for (int i = t; i < OUT_N / 4; i += gridDim.x * blockDim.x)
        reinterpret_cast<float4*>(out)[i] = z;
}

__global__ void k_fill_P(float* out) {
    int i = blockIdx.x * blockDim.x + threadIdx.x;
    if (i < NN) out[P_OFF + i * MSUP + g_labels[i]] = g_wnode[i];
}

__global__ void k_xcoarse(const float* __restrict__ X, float* out) {
    int t = blockIdx.x * blockDim.x + threadIdx.x;
    if (t < NN * DF) {
        int i = t >> 9, d = t & (DF - 1);
        atomicAdd(&out[XC_OFF + g_labels[i] * DF + d], g_wnode[i] * X[t]);
    }
}

__global__ void k_acoarse(const float* __restrict__ A, float* out) {
    int warp = (blockIdx.x * blockDim.x + threadIdx.x) >> 5;
    int lane = threadIdx.x & 31;
    if (warp >= NN) return;
    int i = warp;
    int d = min(g_deg[i], MAXDEG);
    float wi = g_wnode[i];
    int li = g_labels[i];
    for (int a = lane; a < d; a += 32) {
        int j = g_adj[i * MAXDEG + a];
        float v = A[(size_t)i * NN + j];
        atomicAdd(&out[AC_OFF + li * MSUP + g_labels[j]], wi * g_wnode[j] * v);
    }
}

// -------- launch --------
extern "C" void kernel_launch(void* const* d_in, const int* in_sizes, int n_in,
                              void* d_out, int out_size) {
    const float* X = (const float*)d_in[0];
    const float* A = (const float*)d_in[1];
    float* out = (float*)d_out;

    k_adj<<<NN / 8, 256>>>(A);
    k_zeroscratch<<<512, 256>>>();
    k_rank<<<NCOMB / 16, 1024>>>();
    k_tri<<<NN / 8, 256>>>();
    k_count<<<NN, 256>>>();
    k_s1<<<NPART, 1024>>>();
    k_s2<<<1, 1024>>>();
    k_s3<<<NPART, 1024>>>();
    k_scatter<<<NN, 256>>>();
    k_subsort<<<256, 1024>>>();
    k_uf<<<1, 1024>>>();

    k_zero<<<256, 256>>>(out);
    k_fill_P<<<NN / 256, 256>>>(out);
    k_xcoarse<<<(NN * DF) / 256, 256>>>(X, out);
    k_acoarse<<<NN / 8, 256>>>(A, out);
}

// round 5
// speedup vs baseline: 5.0267x; 5.0267x over previous
#include <cuda_runtime.h>
#include <cstdint>

// Problem constants (fixed by the reference)
#define NN      2048
#define DF      512
#define MSUP    512
#define TARGET  1536          // N - NUM_SUPER merges
#define MAXDEG  512
#define MAXE    (1 << 21)     // edge-list capacity (positives ~400k expected)
#define INF64   0xFFFFFFFFFFFFFFFFULL

// Output layout: X_coarse [512,512] | A_coarse [512,512] | P [2048,512]
#define XC_OFF  0
#define AC_OFF  262144
#define P_OFF   524288
#define OUT_N   1572864

// -------- scratch (device globals; no allocation allowed) --------
__device__ int                g_adj[NN * MAXDEG];   // 4 MB
__device__ int                g_deg[NN];
__device__ int                g_inter[NN * NN];     // 16 MB (upper triangle)
__device__ unsigned long long g_edges[MAXE];        // 16 MB weighted positive pairs
__device__ int                g_ne;
__device__ int                g_lab[NN];            // Boruvka component labels (roots)
__device__ unsigned long long g_mine[NN];           // per-root min outgoing edge
__device__ unsigned long long g_tlist[4096];        // collected MSF edges (<= 2047)
__device__ int                g_tn;
__device__ int                g_rminfb[NN];         // fallback scratch
__device__ int                g_labels[NN];
__device__ float              g_wnode[NN];

// -------- 1) adjacency lists + degrees (warp per row, ascending j) --------
__global__ void k_adj(const float* __restrict__ A) {
    int warp = (blockIdx.x * blockDim.x + threadIdx.x) >> 5;
    int lane = threadIdx.x & 31;
    if (warp >= NN) return;
    const float* row = A + (size_t)warp * NN;
    int cnt = 0;
    for (int k = 0; k < NN; k += 32) {
        float v = row[k + lane];
        unsigned b = __ballot_sync(0xFFFFFFFFu, v > 0.0f);
        if (v > 0.0f) {
            int pos = cnt + __popc(b & ((1u << lane) - 1u));
            if (pos < MAXDEG) g_adj[warp * MAXDEG + pos] = k + lane;
        }
        cnt += __popc(b);
    }
    if (lane == 0) g_deg[warp] = cnt;
}

// -------- 2) zero/init scratch --------
__global__ void k_zeroscratch() {
    size_t t = (size_t)blockIdx.x * blockDim.x + threadIdx.x;
    size_t stride = (size_t)gridDim.x * blockDim.x;
    int4 z = make_int4(0, 0, 0, 0);
    for (size_t i = t; i < (size_t)NN * NN / 4; i += stride)
        reinterpret_cast<int4*>(g_inter)[i] = z;
    for (size_t i = t; i < NN; i += stride) {
        g_lab[i] = (int)i;
        g_mine[i] = INF64;
    }
    if (t == 0) { g_ne = 0; g_tn = 0; }
}

// -------- 3) sparse triangle counting: inter[i][j] += 1 per shared neighbor --------
__global__ void k_tri() {
    int warp = (blockIdx.x * blockDim.x + threadIdx.x) >> 5;
    int lane = threadIdx.x & 31;
    if (warp >= NN) return;
    int d = min(g_deg[warp], MAXDEG);
    const int* nb = &g_adj[warp * MAXDEG];
    for (int a = 0; a < d - 1; a++) {
        int i = nb[a];                    // ascending list => i < j below
        int* irow = &g_inter[i * NN];
        for (int b = a + 1 + lane; b < d; b += 32)
            atomicAdd(&irow[nb[b]], 1);
    }
}

// -------- 4) extract weighted positive pairs (unordered) --------
// weight ascending == (jaccard descending, then pair index ascending):
//   weight = (~float_bits(jac) << 22) | (i*2048 + j), 54 bits, all distinct.
__global__ void k_edges() {
    __shared__ int sdeg[NN];
    int i = blockIdx.x;
    for (int t = threadIdx.x; t < NN; t += blockDim.x) sdeg[t] = g_deg[t];
    __syncthreads();
    if (i >= NN - 1) return;
    int di = sdeg[i];
    const int* irow = &g_inter[i * NN];
    for (int j = i + 1 + threadIdx.x; j < NN; j += blockDim.x) {
        int inter = irow[j];
        if (inter > 0) {
            int uni = di + sdeg[j] - inter;       // > 0 when inter > 0
            float jac = __fdiv_rn((float)inter, (float)uni);  // bit-exact vs ref
            unsigned fb = __float_as_uint(jac);
            unsigned long long w =
                ((unsigned long long)(~fb) << 22) | (unsigned)(i * NN + j);
            int p = atomicAdd(&g_ne, 1);
            if (p < MAXE) g_edges[p] = w;
        }
    }
}

// -------- 5) Boruvka sweep: per-root min outgoing edge --------
__global__ void k_bsweep() {
    __shared__ int slab[NN];
    int tid = threadIdx.x;
    for (int t = tid; t < NN; t += blockDim.x) slab[t] = g_lab[t];
    __syncthreads();
    int ne = min(g_ne, MAXE);
    for (int e = blockIdx.x * blockDim.x + tid; e < ne; e += gridDim.x * blockDim.x) {
        unsigned long long w = g_edges[e];
        unsigned idx = (unsigned)(w & 0x3FFFFFu);
        int u = idx >> 11, v = idx & (NN - 1);
        int ru = slab[u], rv = slab[v];
        if (ru != rv) {
            atomicMin(&g_mine[ru], w);
            atomicMin(&g_mine[rv], w);
        }
    }
}

// -------- 6) Boruvka hook + collect tree edges + pointer jumping --------
__global__ void k_bhook() {
    __shared__ int slab[NN];
    __shared__ int snew[NN];
    int tid = threadIdx.x;
    for (int t = tid; t < NN; t += 1024) { slab[t] = g_lab[t]; snew[t] = -1; }
    __syncthreads();
    // phase 1: decide hooks (reads only; all g_mine stable)
    for (int r = tid; r < NN; r += 1024) {
        if (slab[r] == r) {
            unsigned long long w = g_mine[r];
            if (w != INF64) {
                unsigned idx = (unsigned)(w & 0x3FFFFFu);
                int u = idx >> 11, v = idx & (NN - 1);
                int ru = slab[u], rv = slab[v];
                int o = (ru == r) ? rv : ru;
                bool mutual = (g_mine[o] == w);   // distinct weights => same edge
                if (!mutual || r > o) snew[r] = o;            // break 2-cycles
                if (!mutual || r < o) {                       // append exactly once
                    int p = atomicAdd(&g_tn, 1);
                    if (p < 4096) g_tlist[p] = w;
                }
            }
        }
    }
    __syncthreads();
    // phase 2: apply hooks, reset minedge
    for (int r = tid; r < NN; r += 1024) {
        if (snew[r] >= 0) slab[r] = snew[r];
        g_mine[r] = INF64;
    }
    __syncthreads();
    // phase 3: pointer jumping to full compression
    for (int it = 0; it < 11; it++) {
        for (int t = tid; t < NN; t += 1024) snew[t] = slab[slab[t]];
        __syncthreads();
        for (int t = tid; t < NN; t += 1024) slab[t] = snew[t];
        __syncthreads();
    }
    for (int t = tid; t < NN; t += 1024) g_lab[t] = slab[t];
}

// -------- 7) finisher: sort MSF edges, CC of first 1536, labels + weights --------
__device__ __forceinline__ int ser_find(int* p, int x) {
    while (p[x] != x) { p[x] = p[p[x]]; x = p[x]; }
    return x;
}

__global__ void k_finish() {
    __shared__ unsigned long long tl[2048];
    __shared__ int lab2[NN];
    __shared__ int mlist[MSUP];
    __shared__ int ssz[MSUP];
    __shared__ float swc[MSUP];
    __shared__ int s_cnt;
    int tid = threadIdx.x;
    int T = min(g_tn, 2047);

    for (int t = tid; t < 2048; t += 1024) tl[t] = (t < T) ? g_tlist[t] : INF64;
    for (int t = tid; t < NN; t += 1024) lab2[t] = t;
    for (int t = tid; t < MSUP; t += 1024) { ssz[t] = 0; mlist[t] = 0x7FFFFFFF; }
    if (tid == 0) s_cnt = 0;
    __syncthreads();

    // bitonic sort 2048 tree edges ascending by weight
    for (int k = 2; k <= 2048; k <<= 1)
        for (int j = k >> 1; j > 0; j >>= 1) {
            for (int t = tid; t < 2048; t += 1024) {
                int x = t ^ j;
                if (x > t) {
                    unsigned long long a = tl[t], b = tl[x];
                    if (((t & k) == 0) ? (a > b) : (a < b)) { tl[t] = b; tl[x] = a; }
                }
            }
            __syncthreads();
        }

    if (T >= TARGET) {
        // partition = CC of the first TARGET Kruskal-accepted edges.
        // min-label propagation + pointer jumping => lab2[v] = min node of comp.
        for (int round = 0; round < 22; round++) {
            for (int e = tid; e < TARGET; e += 1024) {
                unsigned idx = (unsigned)(tl[e] & 0x3FFFFFu);
                int u = idx >> 11, v = idx & (NN - 1);
                int a = lab2[u], b = lab2[v];
                int m = min(a, b);
                if (a != m) atomicMin(&lab2[u], m);
                if (b != m) atomicMin(&lab2[v], m);
            }
            __syncthreads();
            for (int t = tid; t < NN; t += 1024) lab2[t] = lab2[lab2[t]];
            __syncthreads();
        }
    } else {
        // fallback (never expected): apply all T tree edges serially, then
        // continue Kruskal over zero-jaccard pairs in natural index order.
        if (tid == 0) {
            int merged = 0;
            for (int e = 0; e < T && merged < TARGET; e++) {
                unsigned idx = (unsigned)(tl[e] & 0x3FFFFFu);
                int u = idx >> 11, v = idx & (NN - 1);
                int ru = ser_find(lab2, u), rv = ser_find(lab2, v);
                if (ru != rv) { lab2[rv] = ru; merged++; }
            }
            for (int i = 0; i < NN - 1 && merged < TARGET; i++)
                for (int j = i + 1; j < NN && merged < TARGET; j++)
                    if (g_inter[i * NN + j] == 0) {
                        int ri = ser_find(lab2, i), rj = ser_find(lab2, j);
                        if (ri != rj) { lab2[rj] = ri; merged++; }
                    }
            for (int v = 0; v < NN; v++) g_rminfb[v] = NN;
            for (int v = 0; v < NN; v++) {
                int r = ser_find(lab2, v);
                if (v < g_rminfb[r]) g_rminfb[r] = v;
            }
            for (int v = 0; v < NN; v++) g_labels[v] = g_rminfb[ser_find(lab2, v)];
        }
        __syncthreads();
        for (int t = tid; t < NN; t += 1024) lab2[t] = g_labels[t]; // min-node comp id
        __syncthreads();
    }

    // collect the MSUP component minima, sort, rank -> labels 0..511 in
    // first-occurrence order (component label = rank of its min node)
    for (int v = tid; v < NN; v += 1024)
        if (lab2[v] == v) mlist[atomicAdd(&s_cnt, 1)] = v;
    __syncthreads();
    for (int k = 2; k <= MSUP; k <<= 1)
        for (int j = k >> 1; j > 0; j >>= 1) {
            for (int t = tid; t < MSUP; t += 1024) {
                int x = t ^ j;
                if (x > t) {
                    int a = mlist[t], b = mlist[x];
                    if (((t & k) == 0) ? (a > b) : (a < b)) { mlist[t] = b; mlist[x] = a; }
                }
            }
            __syncthreads();
        }
    for (int v = tid; v < NN; v += 1024) {
        int m = lab2[v];
        int lo = 0, hi = MSUP - 1;
        while (lo < hi) { int mid = (lo + hi) >> 1; if (mlist[mid] < m) lo = mid + 1; else hi = mid; }
        g_labels[v] = lo;
        atomicAdd(&ssz[lo], 1);
    }
    __syncthreads();
    for (int t = tid; t < MSUP; t += 1024)
        swc[t] = 1.0f / sqrtf((float)ssz[t] + 1e-10f);
    __syncthreads();
    for (int v = tid; v < NN; v += 1024)
        g_wnode[v] = swc[g_labels[v]];
}

// -------- 8) epilogue --------
__global__ void k_zero(float* out) {
    int t = blockIdx.x * blockDim.x + threadIdx.x;
    float4 z = make_float4(0.f, 0.f, 0.f, 0.f);
    for (int i = t; i < OUT_N / 4; i += gridDim.x * blockDim.x)
        reinterpret_cast<float4*>(out)[i] = z;
}

__global__ void k_fill_P(float* out) {
    int i = blockIdx.x * blockDim.x + threadIdx.x;
    if (i < NN) out[P_OFF + i * MSUP + g_labels[i]] = g_wnode[i];
}

__global__ void k_xcoarse(const float* __restrict__ X, float* out) {
    int t = blockIdx.x * blockDim.x + threadIdx.x;
    if (t < NN * DF) {
        int i = t >> 9, d = t & (DF - 1);
        atomicAdd(&out[XC_OFF + g_labels[i] * DF + d], g_wnode[i] * X[t]);
    }
}

__global__ void k_acoarse(const float* __restrict__ A, float* out) {
    int warp = (blockIdx.x * blockDim.x + threadIdx.x) >> 5;
    int lane = threadIdx.x & 31;
    if (warp >= NN) return;
    int i = warp;
    int d = min(g_deg[i], MAXDEG);
    float wi = g_wnode[i];
    int li = g_labels[i];
    for (int a = lane; a < d; a += 32) {
        int j = g_adj[i * MAXDEG + a];
        float v = A[(size_t)i * NN + j];
        atomicAdd(&out[AC_OFF + li * MSUP + g_labels[j]], wi * g_wnode[j] * v);
    }
}

// -------- launch --------
extern "C" void kernel_launch(void* const* d_in, const int* in_sizes, int n_in,
                              void* d_out, int out_size) {
    const float* X = (const float*)d_in[0];
    const float* A = (const float*)d_in[1];
    float* out = (float*)d_out;

    k_adj<<<NN / 8, 256>>>(A);
    k_zeroscratch<<<512, 256>>>();
    k_tri<<<NN / 8, 256>>>();
    k_edges<<<NN, 256>>>();

    // Boruvka: components at least halve per iteration; 11 covers 2048 -> 1.
    for (int it = 0; it < 11; it++) {
        k_bsweep<<<148, 256>>>();
        k_bhook<<<1, 1024>>>();
    }
    k_finish<<<1, 1024>>>();

    k_zero<<<256, 256>>>(out);
    k_fill_P<<<NN / 256, 256>>>(out);
    k_xcoarse<<<(NN * DF) / 256, 256>>>(X, out);
    k_acoarse<<<NN / 8, 256>>>(A, out);
}

// round 6
// speedup vs baseline: 5.9533x; 1.1843x over previous
#include <cuda_runtime.h>
#include <cstdint>

// Problem constants (fixed by the reference)
#define NN      2048
#define DF      512
#define MSUP    512
#define TARGET  1536          // N - NUM_SUPER merges
#define MAXDEG  512
#define MAXE    (1 << 21)     // edge-list capacity (positives ~400k expected)
#define INF64   0xFFFFFFFFFFFFFFFFULL

// Output layout: X_coarse [512,512] | A_coarse [512,512] | P [2048,512]
#define XC_OFF  0
#define AC_OFF  262144
#define P_OFF   524288
#define OUT_N   1572864

// -------- scratch (device globals; no allocation allowed) --------
__device__ int                g_adj[NN * MAXDEG];   // 4 MB
__device__ int                g_deg[NN];
__device__ int                g_inter[NN * NN];     // 16 MB (upper triangle)
__device__ unsigned long long g_edges[MAXE];        // 16 MB weighted positive pairs
__device__ int                g_ne;
__device__ int                g_lab[NN];            // Boruvka component labels
__device__ unsigned long long g_mine[NN];           // per-root min outgoing edge
__device__ unsigned long long g_tlist[4096];        // collected MSF edges (<= 2047)
__device__ int                g_tn;
__device__ int                g_active;             // hooks performed last round
__device__ int                g_rminfb[NN];         // fallback scratch
__device__ int                g_labels[NN];
__device__ float              g_wnode[NN];

// -------- 1) adjacency lists + degrees (warp per row, ascending j) --------
__global__ void k_adj(const float* __restrict__ A) {
    int warp = (blockIdx.x * blockDim.x + threadIdx.x) >> 5;
    int lane = threadIdx.x & 31;
    if (warp >= NN) return;
    const float* row = A + (size_t)warp * NN;
    int cnt = 0;
    for (int k = 0; k < NN; k += 32) {
        float v = row[k + lane];
        unsigned b = __ballot_sync(0xFFFFFFFFu, v > 0.0f);
        if (v > 0.0f) {
            int pos = cnt + __popc(b & ((1u << lane) - 1u));
            if (pos < MAXDEG) g_adj[warp * MAXDEG + pos] = k + lane;
        }
        cnt += __popc(b);
    }
    if (lane == 0) g_deg[warp] = cnt;
}

// -------- 2) zero/init scratch --------
__global__ void k_zeroscratch() {
    size_t t = (size_t)blockIdx.x * blockDim.x + threadIdx.x;
    size_t stride = (size_t)gridDim.x * blockDim.x;
    int4 z = make_int4(0, 0, 0, 0);
    for (size_t i = t; i < (size_t)NN * NN / 4; i += stride)
        reinterpret_cast<int4*>(g_inter)[i] = z;
    for (size_t i = t; i < NN; i += stride) {
        g_lab[i] = (int)i;
        g_mine[i] = INF64;
    }
    if (t == 0) { g_ne = 0; g_tn = 0; g_active = 1; }
}

// -------- 3) sparse triangle counting --------
__global__ void k_tri() {
    int warp = (blockIdx.x * blockDim.x + threadIdx.x) >> 5;
    int lane = threadIdx.x & 31;
    if (warp >= NN) return;
    int d = min(g_deg[warp], MAXDEG);
    const int* nb = &g_adj[warp * MAXDEG];
    for (int a = 0; a < d - 1; a++) {
        int i = nb[a];                    // ascending list => i < j below
        int* irow = &g_inter[i * NN];
        for (int b = a + 1 + lane; b < d; b += 32)
            atomicAdd(&irow[nb[b]], 1);
    }
}

// -------- 4) edge extraction + fused Boruvka sweep #1 --------
// weight ascending == (jaccard descending, then pair index ascending):
//   weight = (~float_bits(jac) << 22) | (i*2048 + j), 54 bits, all distinct.
// Block-aggregated append: ONE global atomicAdd per block (not per edge).
// Labels are identity here, so sweep #1's atomicMin targets u and v directly;
// the i-side is block-reduced to a single atomic.
__global__ void k_edges() {
    __shared__ int sdeg[NN];                    // 8 KB
    __shared__ unsigned long long sbuf[NN];     // 16 KB (row has < NN positives)
    __shared__ unsigned long long sred[256];    // 2 KB
    __shared__ int scnt, sbase;
    int i = blockIdx.x;
    int tid = threadIdx.x;
    for (int t = tid; t < NN; t += blockDim.x) sdeg[t] = g_deg[t];
    if (tid == 0) scnt = 0;
    __syncthreads();
    if (i >= NN - 1) return;

    int di = sdeg[i];
    const int* irow = &g_inter[i * NN];
    unsigned long long wmin = INF64;
    for (int j = i + 1 + tid; j < NN; j += blockDim.x) {
        int inter = irow[j];
        if (inter > 0) {
            int uni = di + sdeg[j] - inter;   // > 0 when inter > 0
            float jac = __fdiv_rn((float)inter, (float)uni);  // bit-exact vs ref
            unsigned fb = __float_as_uint(jac);
            unsigned long long w =
                ((unsigned long long)(~fb) << 22) | (unsigned)(i * NN + j);
            int p = atomicAdd(&scnt, 1);      // shared atomic: cheap
            sbuf[p] = w;
            wmin = min(wmin, w);
            atomicMin(&g_mine[j], w);         // sweep #1, v-side
        }
    }
    // block-reduce the i-side min
    sred[tid] = wmin;
    __syncthreads();
    for (int d = 128; d > 0; d >>= 1) {
        if (tid < d) sred[tid] = min(sred[tid], sred[tid + d]);
        __syncthreads();
    }
    if (tid == 0) {
        if (sred[0] != INF64) atomicMin(&g_mine[i], sred[0]);
        sbase = atomicAdd(&g_ne, scnt);       // ONE global atomic per block
    }
    __syncthreads();
    int base = sbase, n = scnt;
    for (int t = tid; t < n; t += blockDim.x)
        if (base + t < MAXE) g_edges[base + t] = sbuf[t];
}

// -------- 5) Boruvka sweep: per-root min outgoing edge (early-exit) --------
__global__ void k_bsweep() {
    if (g_active == 0) return;
    __shared__ int slab[NN];
    int tid = threadIdx.x;
    for (int t = tid; t < NN; t += blockDim.x) slab[t] = g_lab[t];
    __syncthreads();
    int ne = min(g_ne, MAXE);
    for (int e = blockIdx.x * blockDim.x + tid; e < ne; e += gridDim.x * blockDim.x) {
        unsigned long long w = g_edges[e];
        unsigned idx = (unsigned)(w & 0x3FFFFFu);
        int u = idx >> 11, v = idx & (NN - 1);
        int ru = slab[u], rv = slab[v];
        if (ru != rv) {
            atomicMin(&g_mine[ru], w);
            atomicMin(&g_mine[rv], w);
        }
    }
}

// -------- 6) Boruvka hook + collect tree edges + pointer jumping --------
__global__ void k_bhook() {
    if (g_active == 0) return;
    __shared__ int slab[NN];
    __shared__ int snew[NN];
    __shared__ int s_h;
    int tid = threadIdx.x;
    for (int t = tid; t < NN; t += 1024) { slab[t] = g_lab[t]; snew[t] = -1; }
    if (tid == 0) s_h = 0;
    __syncthreads();
    // phase 1: decide hooks (reads only; g_mine stable at kernel boundary)
    for (int r = tid; r < NN; r += 1024) {
        if (slab[r] == r) {
            unsigned long long w = g_mine[r];
            if (w != INF64) {
                unsigned idx = (unsigned)(w & 0x3FFFFFu);
                int u = idx >> 11, v = idx & (NN - 1);
                int ru = slab[u], rv = slab[v];
                int o = (ru == r) ? rv : ru;
                bool mutual = (g_mine[o] == w);   // distinct weights => same edge
                if (!mutual || r > o) { snew[r] = o; atomicAdd(&s_h, 1); }
                if (!mutual || r < o) {           // append tree edge exactly once
                    int p = atomicAdd(&g_tn, 1);
                    if (p < 4096) g_tlist[p] = w;
                }
            }
        }
    }
    __syncthreads();
    // phase 2: apply hooks, reset minedge
    for (int r = tid; r < NN; r += 1024) {
        if (snew[r] >= 0) slab[r] = snew[r];
        g_mine[r] = INF64;
    }
    __syncthreads();
    // phase 3: pointer jumping to full compression
    for (int it = 0; it < 11; it++) {
        for (int t = tid; t < NN; t += 1024) snew[t] = slab[slab[t]];
        __syncthreads();
        for (int t = tid; t < NN; t += 1024) slab[t] = snew[t];
        __syncthreads();
    }
    for (int t = tid; t < NN; t += 1024) g_lab[t] = slab[t];
    if (tid == 0) g_active = s_h;     // 0 => MSF complete; later rounds no-op
}

// -------- 7) finisher: sort MSF edges, CC of first 1536, labels + weights --------
__device__ __forceinline__ int ser_find(int* p, int x) {
    while (p[x] != x) { p[x] = p[p[x]]; x = p[x]; }
    return x;
}

__global__ void k_finish() {
    __shared__ unsigned long long tl[2048];
    __shared__ int lab2[NN];
    __shared__ int mlist[MSUP];
    __shared__ int ssz[MSUP];
    __shared__ float swc[MSUP];
    __shared__ int s_cnt;
    int tid = threadIdx.x;
    int T = min(g_tn, 2047);

    for (int t = tid; t < 2048; t += 1024) tl[t] = (t < T) ? g_tlist[t] : INF64;
    for (int t = tid; t < NN; t += 1024) lab2[t] = t;
    for (int t = tid; t < MSUP; t += 1024) { ssz[t] = 0; mlist[t] = 0x7FFFFFFF; }
    if (tid == 0) s_cnt = 0;
    __syncthreads();

    // bitonic sort 2048 tree edges ascending by weight
    for (int k = 2; k <= 2048; k <<= 1)
        for (int j = k >> 1; j > 0; j >>= 1) {
            for (int t = tid; t < 2048; t += 1024) {
                int x = t ^ j;
                if (x > t) {
                    unsigned long long a = tl[t], b = tl[x];
                    if (((t & k) == 0) ? (a > b) : (a < b)) { tl[t] = b; tl[x] = a; }
                }
            }
            __syncthreads();
        }

    if (T >= TARGET) {
        // partition = CC of the first TARGET Kruskal-accepted edges.
        for (int round = 0; round < 22; round++) {
            for (int e = tid; e < TARGET; e += 1024) {
                unsigned idx = (unsigned)(tl[e] & 0x3FFFFFu);
                int u = idx >> 11, v = idx & (NN - 1);
                int a = lab2[u], b = lab2[v];
                int m = min(a, b);
                if (a != m) atomicMin(&lab2[u], m);
                if (b != m) atomicMin(&lab2[v], m);
            }
            __syncthreads();
            for (int t = tid; t < NN; t += 1024) lab2[t] = lab2[lab2[t]];
            __syncthreads();
        }
    } else {
        // fallback (never expected): serial Kruskal tail incl. zero-jaccard pairs
        if (tid == 0) {
            int merged = 0;
            for (int e = 0; e < T && merged < TARGET; e++) {
                unsigned idx = (unsigned)(tl[e] & 0x3FFFFFu);
                int u = idx >> 11, v = idx & (NN - 1);
                int ru = ser_find(lab2, u), rv = ser_find(lab2, v);
                if (ru != rv) { lab2[rv] = ru; merged++; }
            }
            for (int i = 0; i < NN - 1 && merged < TARGET; i++)
                for (int j = i + 1; j < NN && merged < TARGET; j++)
                    if (g_inter[i * NN + j] == 0) {
                        int ri = ser_find(lab2, i), rj = ser_find(lab2, j);
                        if (ri != rj) { lab2[rj] = ri; merged++; }
                    }
            for (int v = 0; v < NN; v++) g_rminfb[v] = NN;
            for (int v = 0; v < NN; v++) {
                int r = ser_find(lab2, v);
                if (v < g_rminfb[r]) g_rminfb[r] = v;
            }
            for (int v = 0; v < NN; v++) g_labels[v] = g_rminfb[ser_find(lab2, v)];
        }
        __syncthreads();
        for (int t = tid; t < NN; t += 1024) lab2[t] = g_labels[t];
        __syncthreads();
    }

    // component minima -> sorted -> rank == first-occurrence label
    for (int v = tid; v < NN; v += 1024)
        if (lab2[v] == v) mlist[atomicAdd(&s_cnt, 1)] = v;
    __syncthreads();
    for (int k = 2; k <= MSUP; k <<= 1)
        for (int j = k >> 1; j > 0; j >>= 1) {
            for (int t = tid; t < MSUP; t += 1024) {
                int x = t ^ j;
                if (x > t) {
                    int a = mlist[t], b = mlist[x];
                    if (((t & k) == 0) ? (a > b) : (a < b)) { mlist[t] = b; mlist[x] = a; }
                }
            }
            __syncthreads();
        }
    for (int v = tid; v < NN; v += 1024) {
        int m = lab2[v];
        int lo = 0, hi = MSUP - 1;
        while (lo < hi) { int mid = (lo + hi) >> 1; if (mlist[mid] < m) lo = mid + 1; else hi = mid; }
        g_labels[v] = lo;
        atomicAdd(&ssz[lo], 1);
    }
    __syncthreads();
    for (int t = tid; t < MSUP; t += 1024)
        swc[t] = 1.0f / sqrtf((float)ssz[t] + 1e-10f);
    __syncthreads();
    for (int v = tid; v < NN; v += 1024)
        g_wnode[v] = swc[g_labels[v]];
}

// -------- 8) epilogue --------
__global__ void k_zero(float* out) {
    int t = blockIdx.x * blockDim.x + threadIdx.x;
    float4 z = make_float4(0.f, 0.f, 0.f, 0.f);
    for (int i = t; i < OUT_N / 4; i += gridDim.x * blockDim.x)
        reinterpret_cast<float4*>(out)[i] = z;
}

__global__ void k_fill_P(float* out) {
    int i = blockIdx.x * blockDim.x + threadIdx.x;
    if (i < NN) out[P_OFF + i * MSUP + g_labels[i]] = g_wnode[i];
}

__global__ void k_xcoarse(const float* __restrict__ X, float* out) {
    int t = blockIdx.x * blockDim.x + threadIdx.x;
    if (t < NN * DF) {
        int i = t >> 9, d = t & (DF - 1);
        atomicAdd(&out[XC_OFF + g_labels[i] * DF + d], g_wnode[i] * X[t]);
    }
}

__global__ void k_acoarse(const float* __restrict__ A, float* out) {
    int warp = (blockIdx.x * blockDim.x + threadIdx.x) >> 5;
    int lane = threadIdx.x & 31;
    if (warp >= NN) return;
    int i = warp;
    int d = min(g_deg[i], MAXDEG);
    float wi = g_wnode[i];
    int li = g_labels[i];
    for (int a = lane; a < d; a += 32) {
        int j = g_adj[i * MAXDEG + a];
        float v = A[(size_t)i * NN + j];
        atomicAdd(&out[AC_OFF + li * MSUP + g_labels[j]], wi * g_wnode[j] * v);
    }
}

// -------- launch --------
extern "C" void kernel_launch(void* const* d_in, const int* in_sizes, int n_in,
                              void* d_out, int out_size) {
    const float* X = (const float*)d_in[0];
    const float* A = (const float*)d_in[1];
    float* out = (float*)d_out;

    k_zero<<<256, 256>>>(out);          // no deps; get it out of the way
    k_adj<<<NN / 8, 256>>>(A);
    k_zeroscratch<<<512, 256>>>();
    k_tri<<<NN / 8, 256>>>();
    k_edges<<<NN, 256>>>();             // includes Boruvka sweep #1

    k_bhook<<<1, 1024>>>();             // hook #1 -> <= 1024 components
    for (int it = 0; it < 10; it++) {   // halving guarantees completion
        k_bsweep<<<148, 256>>>();
        k_bhook<<<1, 1024>>>();
    }
    k_finish<<<1, 1024>>>();

    k_fill_P<<<NN / 256, 256>>>(out);
    k_xcoarse<<<(NN * DF) / 256, 256>>>(X, out);
    k_acoarse<<<NN / 8, 256>>>(A, out);
}